// round 1
// baseline (speedup 1.0000x reference)
#include <cuda_runtime.h>
#include <cstdint>

#define BB 4
#define CIN 128
#define CO 64
#define HH 128
#define WW 128
#define HW (HH*WW)

// ---------------- scratch (device globals; no allocation) ----------------
__device__ float g_y   [BB*CO*HW];          // current branch conv output (scaled)
__device__ float g_off [BB*18*HW];          // offsets (18 ch)
__device__ float g_f   [BB*4*CO*HW];        // combined deform features (256 ch)
__device__ float g_wtb [4*CIN*9*CO];        // branch weights transposed [(ic*9+tap)*64+oc]
__device__ float g_wtp [CO*9*18];           // p_w transposed [(ic*9+tap)*18+oc]
__device__ float g_dwt [CO*9*CO];           // dw transposed [(c*9+n)*64+oc]
__device__ float g_cwt [4*CO*CO];           // cw transposed [k*64+oc]

// ---------------- one-time weight transposes ----------------
__global__ void transpose_kernel(const float* __restrict__ w1, const float* __restrict__ w2,
                                 const float* __restrict__ w3, const float* __restrict__ w4,
                                 const float* __restrict__ pw, const float* __restrict__ dw,
                                 const float* __restrict__ cw)
{
    int tid = blockIdx.x*blockDim.x + threadIdx.x;
    int nt  = gridDim.x*blockDim.x;
    const float* wb[4] = {w1,w2,w3,w4};
    for (int br = 0; br < 4; br++) {
        const float* w = wb[br];
        for (int i = tid; i < CO*CIN*9; i += nt) {
            int oc = i / (CIN*9); int r = i - oc*(CIN*9);   // r = ic*9+tap
            g_wtb[br*(CIN*9*CO) + r*CO + oc] = w[i];
        }
    }
    for (int i = tid; i < 18*CO*9; i += nt) {
        int oc = i / (CO*9); int r = i - oc*(CO*9);
        g_wtp[r*18 + oc] = pw[i];
    }
    for (int i = tid; i < CO*CO*9; i += nt) {
        int oc = i / (CO*9); int r = i - oc*(CO*9);
        g_dwt[r*CO + oc] = dw[i];
    }
    for (int i = tid; i < CO*4*CO; i += nt) {
        int oc = i >> 8; int k = i & 255;
        g_cwt[k*CO + oc] = cw[i];
    }
}

// ---------------- dilated 3x3 conv (16 oc x 16 rows x 32 cols per block) ----------------
// mode 0: in = xext (B,CIN,H,W), weights g_wtb[widx], out g_y,  y=(conv+b)*scale
// mode 1: in = g_y  (B,64,H,W),  weights g_wtp,       out g_off
template<int DIL>
__global__ void conv3x3_kernel(const float* __restrict__ xext,
                               const float* __restrict__ bias,
                               int cin, int cout, float scale, int mode, int widx)
{
    constexpr int XW  = 32 + 2*DIL;
    constexpr int SXW = XW + 1;           // odd stride -> conflict-free LDS
    constexpr int SXH = 16 + 2*DIL;
    __shared__ __align__(16) float sx[SXH*SXW];
    __shared__ __align__(16) float sw[144];

    const float* in  = mode ? g_y  : xext;
    const float* wt  = mode ? g_wtp : (g_wtb + (size_t)widx*(CIN*9*CO));
    float*       outp= mode ? g_off : g_y;

    int tx = threadIdx.x, ty = threadIdx.y;
    int tid = ty*8 + tx;
    int col0 = blockIdx.x*32, row0 = blockIdx.y*16;
    int ocgn = (cout + 15) >> 4;
    int ocg  = blockIdx.z % ocgn;
    int b    = blockIdx.z / ocgn;
    int oc0  = ocg*16;

    float4 acc[16];
    #pragma unroll
    for (int i = 0; i < 16; i++) acc[i] = make_float4(0.f,0.f,0.f,0.f);

    for (int ic = 0; ic < cin; ic++) {
        const float* xb = in + ((size_t)(b*cin + ic))*HW;
        for (int i = tid; i < SXH*XW; i += 128) {
            int r = i / XW, c = i - r*XW;
            int gy = row0 + r - DIL, gx = col0 + c - DIL;
            float v = 0.f;
            if ((unsigned)gy < (unsigned)HH && (unsigned)gx < (unsigned)WW) v = xb[gy*WW + gx];
            sx[r*SXW + c] = v;
        }
        {
            const float* wrow = wt + (size_t)ic*9*cout;
            for (int i = tid; i < 144; i += 128) {
                int tap = i >> 4, j = i & 15;
                int oc = oc0 + j;
                sw[i] = (oc < cout) ? wrow[tap*cout + oc] : 0.f;
            }
        }
        __syncthreads();
        #pragma unroll
        for (int ky = 0; ky < 3; ky++) {
            #pragma unroll
            for (int kx = 0; kx < 3; kx++) {
                const float* xr = &sx[(ty + ky*DIL)*SXW + tx*4 + kx*DIL];
                float x0 = xr[0], x1 = xr[1], x2 = xr[2], x3 = xr[3];
                const float4* wq = (const float4*)&sw[(ky*3 + kx)*16];
                #pragma unroll
                for (int q = 0; q < 4; q++) {
                    float4 wv = wq[q];
                    acc[4*q+0].x += wv.x*x0; acc[4*q+0].y += wv.x*x1; acc[4*q+0].z += wv.x*x2; acc[4*q+0].w += wv.x*x3;
                    acc[4*q+1].x += wv.y*x0; acc[4*q+1].y += wv.y*x1; acc[4*q+1].z += wv.y*x2; acc[4*q+1].w += wv.y*x3;
                    acc[4*q+2].x += wv.z*x0; acc[4*q+2].y += wv.z*x1; acc[4*q+2].z += wv.z*x2; acc[4*q+2].w += wv.z*x3;
                    acc[4*q+3].x += wv.w*x0; acc[4*q+3].y += wv.w*x1; acc[4*q+3].z += wv.w*x2; acc[4*q+3].w += wv.w*x3;
                }
            }
        }
        __syncthreads();
    }

    int h = row0 + ty, w_ = col0 + tx*4;
    #pragma unroll
    for (int o = 0; o < 16; o++) {
        int oc = oc0 + o;
        if (oc < cout) {
            float bb = bias[oc];
            float4 r;
            r.x = (acc[o].x + bb)*scale;
            r.y = (acc[o].y + bb)*scale;
            r.z = (acc[o].z + bb)*scale;
            r.w = (acc[o].w + bb)*scale;
            *(float4*)&outp[(((size_t)(b*cout + oc))*HH + h)*WW + w_] = r;
        }
    }
}

// ---------------- deformable sampling + 64x576 matmul, fused ----------------
__device__ __forceinline__ int mkidx(int y, int x) {
    // padded 130x130 image; ring is zero
    if (y == 0 || y == 129 || x == 0 || x == 129) return -1;
    return (y - 1)*WW + (x - 1);
}

__global__ void deform_kernel(const float* __restrict__ db, int br)
{
    __shared__ int   sidx[4][288];
    __shared__ float swt [4][288];
    __shared__ __align__(16) float ssmp[2304];   // [c8][n][px32]
    __shared__ __align__(16) float sdw [4608];   // [c8*9][oc64]

    int tid = threadIdx.x;
    int w0  = blockIdx.x*32;
    int h   = blockIdx.y;
    int b   = blockIdx.z;

    // phase A: per-pixel-per-tap indices and bilinear weights (exact ref formulas)
    for (int t = tid; t < 288; t += 128) {
        int n = t >> 5, px = t & 31;
        int wg = w0 + px;
        const float* offp = g_off + (((size_t)(b*18 + n))*HH + h)*WW + wg;
        float offy = offp[0];
        float offx = offp[9*HW];
        float py  = (float)(h + 1)  + (float)(n/3 - 1) + offy;
        float pxx = (float)(wg + 1) + (float)(n%3 - 1) + offx;
        float fy = floorf(py), fx = floorf(pxx);
        float lty = fminf(fmaxf(fy,       0.f), 129.f);
        float ltx = fminf(fmaxf(fx,       0.f), 129.f);
        float rby = fminf(fmaxf(fy + 1.f, 0.f), 129.f);
        float rbx = fminf(fmaxf(fx + 1.f, 0.f), 129.f);
        float pyc = fminf(fmaxf(py,  0.f), 129.f);
        float pxc = fminf(fmaxf(pxx, 0.f), 129.f);
        float gy1 = 1.f + (lty - pyc), gy2 = 1.f - (rby - pyc);
        float gx1 = 1.f + (ltx - pxc), gx2 = 1.f - (rbx - pxc);
        swt[0][t] = gy1*gx1;  // lt
        swt[1][t] = gy2*gx2;  // rb
        swt[2][t] = gy1*gx2;  // lb = (lt_y, rb_x)
        swt[3][t] = gy2*gx1;  // rt = (rb_y, lt_x)
        int iy0 = (int)lty, ix0 = (int)ltx, iy1 = (int)rby, ix1 = (int)rbx;
        sidx[0][t] = mkidx(iy0, ix0);
        sidx[1][t] = mkidx(iy1, ix1);
        sidx[2][t] = mkidx(iy0, ix1);
        sidx[3][t] = mkidx(iy1, ix0);
    }

    int qp = tid & 7;        // px quad 0..7
    int qo = tid >> 3;       // oc quad 0..15
    float4 acc[4];
    #pragma unroll
    for (int i = 0; i < 4; i++) acc[i] = make_float4(0.f,0.f,0.f,0.f);

    const float* ybase = g_y + (size_t)b*CO*HW;
    __syncthreads();

    for (int c0 = 0; c0 < CO; c0 += 8) {
        // dw chunk (contiguous, coalesced, conflict-free)
        for (int i = tid*4; i < 4608; i += 512)
            *(float4*)&sdw[i] = *(const float4*)&g_dwt[c0*576 + i];
        // gather samples for 8 channels
        for (int u = tid; u < 2304; u += 128) {
            int cc = u / 288;
            int t  = u - cc*288;
            const float* base = ybase + (size_t)(c0 + cc)*HW;
            float v = 0.f;
            int i0 = sidx[0][t]; if (i0 >= 0) v += swt[0][t]*base[i0];
            int i1 = sidx[1][t]; if (i1 >= 0) v += swt[1][t]*base[i1];
            int i2 = sidx[2][t]; if (i2 >= 0) v += swt[2][t]*base[i2];
            int i3 = sidx[3][t]; if (i3 >= 0) v += swt[3][t]*base[i3];
            ssmp[u] = v;
        }
        __syncthreads();
        // matmul: acc[oc4][px4] += dw[r][oc4] * s[r][px4]
        #pragma unroll 8
        for (int r = 0; r < 72; r++) {
            float4 sv = *(const float4*)&ssmp[r*32 + qp*4];
            float4 wv = *(const float4*)&sdw [r*64 + qo*4];
            acc[0].x += wv.x*sv.x; acc[0].y += wv.x*sv.y; acc[0].z += wv.x*sv.z; acc[0].w += wv.x*sv.w;
            acc[1].x += wv.y*sv.x; acc[1].y += wv.y*sv.y; acc[1].z += wv.y*sv.z; acc[1].w += wv.y*sv.w;
            acc[2].x += wv.z*sv.x; acc[2].y += wv.z*sv.y; acc[2].z += wv.z*sv.z; acc[2].w += wv.z*sv.w;
            acc[3].x += wv.w*sv.x; acc[3].y += wv.w*sv.y; acc[3].z += wv.w*sv.z; acc[3].w += wv.w*sv.w;
        }
        __syncthreads();
    }

    int wb = w0 + qp*4;
    #pragma unroll
    for (int i = 0; i < 4; i++) {
        int oc = qo*4 + i;
        float bb = db[oc];
        float4 a = acc[i];
        float4 r;
        r.x = a.x + bb; r.y = a.y + bb; r.z = a.z + bb; r.w = a.w + bb;
        *(float4*)&g_f[(((size_t)(b*4*CO + br*CO + oc))*HH + h)*WW + wb] = r;
    }
}

// ---------------- final 1x1 conv (256 -> 64) + ReLU ----------------
__global__ void final_kernel(const float* __restrict__ cb, float* __restrict__ out)
{
    __shared__ __align__(16) float fs[1024];   // [kk16][px64]
    __shared__ __align__(16) float ws[1024];   // [kk16][oc64]
    int tid = threadIdx.x;
    int p0  = blockIdx.x*64;
    int b   = blockIdx.y;
    int qp = tid & 15, qo = tid >> 4;

    float4 acc[4];
    #pragma unroll
    for (int i = 0; i < 4; i++) acc[i] = make_float4(0.f,0.f,0.f,0.f);

    for (int k0 = 0; k0 < 256; k0 += 16) {
        {
            int i = tid << 2;                 // 256 threads x float4 = 1024
            int kk = i >> 6, px = i & 63;
            *(float4*)&fs[i] = *(const float4*)&g_f[((size_t)(b*256 + k0 + kk))*HW + p0 + px];
            *(float4*)&ws[i] = *(const float4*)&g_cwt[k0*64 + i];
        }
        __syncthreads();
        #pragma unroll
        for (int kk = 0; kk < 16; kk++) {
            float4 sv = *(const float4*)&fs[kk*64 + qp*4];
            float4 wv = *(const float4*)&ws[kk*64 + qo*4];
            acc[0].x += wv.x*sv.x; acc[0].y += wv.x*sv.y; acc[0].z += wv.x*sv.z; acc[0].w += wv.x*sv.w;
            acc[1].x += wv.y*sv.x; acc[1].y += wv.y*sv.y; acc[1].z += wv.y*sv.z; acc[1].w += wv.y*sv.w;
            acc[2].x += wv.z*sv.x; acc[2].y += wv.z*sv.y; acc[2].z += wv.z*sv.z; acc[2].w += wv.z*sv.w;
            acc[3].x += wv.w*sv.x; acc[3].y += wv.w*sv.y; acc[3].z += wv.w*sv.z; acc[3].w += wv.w*sv.w;
        }
        __syncthreads();
    }

    int pp = p0 + qp*4;
    #pragma unroll
    for (int i = 0; i < 4; i++) {
        int oc = qo*4 + i;
        float bb = cb[oc];
        float4 a = acc[i];
        float4 r;
        r.x = fmaxf(a.x + bb, 0.f);
        r.y = fmaxf(a.y + bb, 0.f);
        r.z = fmaxf(a.z + bb, 0.f);
        r.w = fmaxf(a.w + bb, 0.f);
        *(float4*)&out[((size_t)(b*CO + oc))*HW + pp] = r;
    }
}

// ---------------- launch ----------------
extern "C" void kernel_launch(void* const* d_in, const int* in_sizes, int n_in,
                              void* d_out, int out_size)
{
    const float* x   = (const float*)d_in[0];
    const float* w1  = (const float*)d_in[1];
    const float* b1  = (const float*)d_in[2];
    const float* w2  = (const float*)d_in[3];
    const float* b2  = (const float*)d_in[4];
    const float* w3  = (const float*)d_in[5];
    const float* b3  = (const float*)d_in[6];
    const float* w4  = (const float*)d_in[7];
    const float* b4  = (const float*)d_in[8];
    const float* p_w = (const float*)d_in[9];
    const float* p_b = (const float*)d_in[10];
    const float* dw  = (const float*)d_in[11];
    const float* db  = (const float*)d_in[12];
    const float* cw  = (const float*)d_in[13];
    const float* cb  = (const float*)d_in[14];
    float* out = (float*)d_out;

    transpose_kernel<<<128, 256>>>(w1, w2, w3, w4, p_w, dw, cw);

    dim3 cblk(8, 16);
    dim3 gbr(4, 8, 16);   // B * 4 oc-groups
    dim3 goff(4, 8, 8);   // B * 2 oc-groups (18 ch)
    dim3 gdef(4, 128, 4);

    const float* bias[4] = {b1, b2, b3, b4};
    for (int br = 0; br < 4; br++) {
        float s = (float)(2*br + 1);
        switch (br) {
            case 0: conv3x3_kernel<1><<<gbr, cblk>>>(x, bias[0], CIN, CO, s, 0, 0); break;
            case 1: conv3x3_kernel<3><<<gbr, cblk>>>(x, bias[1], CIN, CO, s, 0, 1); break;
            case 2: conv3x3_kernel<5><<<gbr, cblk>>>(x, bias[2], CIN, CO, s, 0, 2); break;
            case 3: conv3x3_kernel<7><<<gbr, cblk>>>(x, bias[3], CIN, CO, s, 0, 3); break;
        }
        conv3x3_kernel<1><<<goff, cblk>>>(x, p_b, CO, 18, 1.f, 1, 0);
        deform_kernel<<<gdef, 128>>>(db, br);
    }
    final_kernel<<<dim3(256, 4), 256>>>(cb, out);
}